// round 4
// baseline (speedup 1.0000x reference)
#include <cuda_runtime.h>
#include <cstdint>

#define B_   8
#define C_   64
#define HW_  4096
#define D_   8
#define TBN  128             // keys per tile
#define NT   (HW_ / TBN)     // 32
#define LOG2E 1.4426950408889634f

// ---------------- device scratch (allocation-free rule) ----------------
__device__ float g_q[B_ * HW_ * D_];   // [b][n][8], pre-scaled by log2e
__device__ float g_k[B_ * HW_ * D_];   // [b][m][8]
__device__ float g_v[B_ * C_ * HW_];   // [b][c][n]  channel-major

// ---------------- smem geometry (attn) ----------------
#define KPITCH  48                    // bytes per key row (12 floats, conflict-free)
#define KBYTES  (TBN * KPITCH)        // 6144
#define VPITCHB 528                   // bytes per chan row (132 floats, conflict-free)
#define VBYTES  (C_ * VPITCHB)        // 33792
#define BUFSZ   (KBYTES + VBYTES)     // 39936
#define SMEM_TOTAL (3 * BUFSZ)        // 119808

// ---------------- helpers ----------------
__device__ __forceinline__ uint32_t smem_u32(const void* p) {
    uint32_t a;
    asm("{ .reg .u64 t; cvta.to.shared.u64 t, %1; cvt.u32.u64 %0, t; }" : "=r"(a) : "l"(p));
    return a;
}
__device__ __forceinline__ float ex2f(float x) {
    float r; asm("ex2.approx.f32 %0, %1;" : "=f"(r) : "f"(x)); return r;
}
__device__ __forceinline__ uint32_t tf32r(float f) {
    uint32_t u; asm("cvt.rna.tf32.f32 %0, %1;" : "=r"(u) : "f"(f)); return u;
}
__device__ __forceinline__ float lds32(uint32_t a) {
    float v; asm volatile("ld.shared.f32 %0, [%1];" : "=f"(v) : "r"(a)); return v;
}
__device__ __forceinline__ void cp16(uint32_t dst, const void* src) {
    asm volatile("cp.async.cg.shared.global [%0], [%1], 16;" :: "r"(dst), "l"(src) : "memory");
}
__device__ __forceinline__ void cp_commit() {
    asm volatile("cp.async.commit_group;" ::: "memory");
}
template <int N>
__device__ __forceinline__ void cp_wait() {
    asm volatile("cp.async.wait_group %0;" :: "n"(N) : "memory");
}
// m16n8k8 row.col f32 += tf32*tf32
__device__ __forceinline__ void mma8(float* c, const uint32_t* a, uint32_t b0, uint32_t b1) {
    asm("mma.sync.aligned.m16n8k8.row.col.f32.tf32.tf32.f32 "
        "{%0,%1,%2,%3},{%4,%5,%6,%7},{%8,%9},{%0,%1,%2,%3};"
        : "+f"(c[0]), "+f"(c[1]), "+f"(c[2]), "+f"(c[3])
        : "r"(a[0]), "r"(a[1]), "r"(a[2]), "r"(a[3]), "r"(b0), "r"(b1));
}

// ---------------- packed f32x2 helpers (proj) ----------------
__device__ __forceinline__ unsigned long long fma2(unsigned long long a,
                                                   unsigned long long b,
                                                   unsigned long long c) {
    unsigned long long d;
    asm("fma.rn.f32x2 %0, %1, %2, %3;" : "=l"(d) : "l"(a), "l"(b), "l"(c));
    return d;
}
__device__ __forceinline__ unsigned long long pack2(float lo, float hi) {
    unsigned long long d;
    asm("mov.b64 %0, {%1, %2};" : "=l"(d) : "f"(lo), "f"(hi));
    return d;
}
__device__ __forceinline__ void unpack2(unsigned long long v, float& lo, float& hi) {
    asm("mov.b64 {%0, %1}, %2;" : "=f"(lo), "=f"(hi) : "l"(v));
}

// ---------------- Kernel 1: 1x1-conv projections ----------------
__global__ __launch_bounds__(256) void proj_kernel(
    const float* __restrict__ query, const float* __restrict__ value,
    const float* __restrict__ Wq, const float* __restrict__ bq,
    const float* __restrict__ Wk, const float* __restrict__ bk,
    const float* __restrict__ Wv, const float* __restrict__ bv) {
    __shared__ __align__(16) float sWqT[C_ * D_];
    __shared__ __align__(16) float sWkT[C_ * D_];
    __shared__ __align__(16) float sWvT[C_ * C_];
    __shared__ float sbq[D_], sbk[D_], sbv[C_];

    const int tid = threadIdx.x;
    for (int i = tid; i < D_ * C_; i += 256) {
        int o = i / C_, c = i % C_;
        sWqT[c * D_ + o] = Wq[i];
        sWkT[c * D_ + o] = Wk[i];
    }
    for (int i = tid; i < C_ * C_; i += 256) {
        int o = i / C_, c = i % C_;
        sWvT[c * C_ + o] = Wv[i];
    }
    if (tid < C_) sbv[tid] = bv[tid];
    if (tid < D_) { sbq[tid] = bq[tid]; sbk[tid] = bk[tid]; }
    __syncthreads();

    const int b = blockIdx.y;
    const int n = blockIdx.x * 256 + tid;
    const float* qbase = query + (size_t)b * C_ * HW_ + n;
    const float* vbase = value + (size_t)b * C_ * HW_ + n;

    float qa[D_], ka[D_];
    unsigned long long va2[C_ / 2];
#pragma unroll
    for (int d = 0; d < D_; ++d) { qa[d] = 0.f; ka[d] = 0.f; }
#pragma unroll
    for (int i = 0; i < C_ / 2; ++i) va2[i] = 0ULL;

#pragma unroll 2
    for (int c = 0; c < C_; ++c) {
        const float x = qbase[(size_t)c * HW_];
        const float y = vbase[(size_t)c * HW_];
        const float4 wq  = *(const float4*)&sWqT[c * D_];
        const float4 wq2 = *(const float4*)&sWqT[c * D_ + 4];
        const float4 wk  = *(const float4*)&sWkT[c * D_];
        const float4 wk2 = *(const float4*)&sWkT[c * D_ + 4];
        qa[0] += wq.x * x;  qa[1] += wq.y * x;  qa[2] += wq.z * x;  qa[3] += wq.w * x;
        qa[4] += wq2.x * x; qa[5] += wq2.y * x; qa[6] += wq2.z * x; qa[7] += wq2.w * x;
        ka[0] += wk.x * x;  ka[1] += wk.y * x;  ka[2] += wk.z * x;  ka[3] += wk.w * x;
        ka[4] += wk2.x * x; ka[5] += wk2.y * x; ka[6] += wk2.z * x; ka[7] += wk2.w * x;
        const unsigned long long y2 = pack2(y, y);
        const ulonglong2* wv = (const ulonglong2*)&sWvT[c * C_];
#pragma unroll
        for (int i = 0; i < C_ / 4; ++i) {
            ulonglong2 w = wv[i];
            va2[2 * i]     = fma2(w.x, y2, va2[2 * i]);
            va2[2 * i + 1] = fma2(w.y, y2, va2[2 * i + 1]);
        }
    }

    const size_t row = (size_t)b * HW_ + n;
    *(float4*)&g_q[row * D_] = make_float4(
        (qa[0] + sbq[0]) * LOG2E, (qa[1] + sbq[1]) * LOG2E,
        (qa[2] + sbq[2]) * LOG2E, (qa[3] + sbq[3]) * LOG2E);
    *(float4*)&g_q[row * D_ + 4] = make_float4(
        (qa[4] + sbq[4]) * LOG2E, (qa[5] + sbq[5]) * LOG2E,
        (qa[6] + sbq[6]) * LOG2E, (qa[7] + sbq[7]) * LOG2E);
    *(float4*)&g_k[row * D_] = make_float4(
        ka[0] + sbk[0], ka[1] + sbk[1], ka[2] + sbk[2], ka[3] + sbk[3]);
    *(float4*)&g_k[row * D_ + 4] = make_float4(
        ka[4] + sbk[4], ka[5] + sbk[5], ka[6] + sbk[6], ka[7] + sbk[7]);

    float* vout = g_v + (size_t)b * C_ * HW_ + n;
#pragma unroll
    for (int i = 0; i < C_ / 2; ++i) {
        float lo, hi;
        unpack2(va2[i], lo, hi);
        vout[(size_t)(2 * i) * HW_]     = lo + sbv[2 * i];
        vout[(size_t)(2 * i + 1) * HW_] = hi + sbv[2 * i + 1];
    }
}

// ---------------- tile loader (512 threads) ----------------
__device__ __forceinline__ void load_tile(uint32_t smb, int buf, int b, int m0, int tid) {
    const uint32_t base = smb + buf * BUFSZ;
    // K: 128 keys x 32B (256 cp16), threads 0..255
    if (tid < 256) {
        const float* ksrc = g_k + ((size_t)b * HW_ + m0) * D_ + tid * 4;
        uint32_t kdst = base + (tid >> 1) * KPITCH + (tid & 1) * 16;
        cp16(kdst, ksrc);
    }
    // V: 64 chans x 512B (2048 cp16), 4 per thread
    const uint32_t vb = base + KBYTES;
    const float* vsrcb = g_v + (size_t)b * C_ * HW_ + m0;
#pragma unroll
    for (int r = 0; r < 4; ++r) {
        int idx = tid + 512 * r;
        int ch = idx >> 5, sg = idx & 31;
        cp16(vb + ch * VPITCHB + sg * 16, vsrcb + (size_t)ch * HW_ + sg * 4);
    }
}

// ---------------- Kernel 2: mma.sync tf32 flash attention ----------------
// CTA: 512 threads, 16 warps x 16 query rows = 256 rows.  Grid: (16, 8).
__global__ __launch_bounds__(512, 1) void attn_kernel(
    const float* __restrict__ value, float* __restrict__ out) {
    extern __shared__ char sm[];
    const uint32_t smb = smem_u32(sm);
    const int tid = threadIdx.x;
    const int w = tid >> 5;
    const int lane = tid & 31;
    const int g = lane >> 2;           // group 0..7
    const int tg = lane & 3;           // thread-in-group 0..3
    const int b = blockIdx.y;
    const int n0 = blockIdx.x * 256;

    // prologue: prefetch tiles 0,1
    load_tile(smb, 0, b, 0, tid);
    cp_commit();
    load_tile(smb, 1, b, TBN, tid);
    cp_commit();

    // Q fragment (A-frag, single m16 tile), rounded to tf32
    const int rbase = n0 + w * 16 + g;   // rows rbase and rbase+8
    uint32_t qa[4];
    {
        const float* q0 = g_q + ((size_t)b * HW_ + rbase) * D_;
        const float* q1 = q0 + 8 * D_;   // row +8
        qa[0] = tf32r(q0[tg]);
        qa[1] = tf32r(q1[tg]);
        qa[2] = tf32r(q0[tg + 4]);
        qa[3] = tf32r(q1[tg + 4]);
    }

    float o[8][4];
#pragma unroll
    for (int ct = 0; ct < 8; ++ct)
#pragma unroll
        for (int i = 0; i < 4; ++i) o[ct][i] = 0.f;
    float rs[2] = {0.f, 0.f};

    // key permutation kappa(g) = (g>>1) + 4*(g&1): makes S C-frag == PV A-frag
    const int kap = (g >> 1) + ((g & 1) << 2);

    for (int t = 0; t < NT; ++t) {
        cp_wait<1>();
        __syncthreads();
        if (t + 2 < NT) load_tile(smb, (t + 2) % 3, b, (t + 2) * TBN, tid);
        cp_commit();

        const uint32_t base = smb + (t % 3) * BUFSZ;
        const uint32_t kbase = base + kap * KPITCH + tg * 4;
        const uint32_t vbase = base + KBYTES + g * VPITCHB + tg * 4;

#pragma unroll 4
        for (int j = 0; j < 16; ++j) {
            const uint32_t ka0 = __float_as_uint(lds32(kbase + j * 8 * KPITCH));
            const uint32_t ka1 = __float_as_uint(lds32(kbase + j * 8 * KPITCH + 16));
            float s[4] = {0.f, 0.f, 0.f, 0.f};
            mma8(s, qa, ka0, ka1);
            // exp2 -> tf32 round -> denom (post-round; bias cancels) -> A-frag
            uint32_t a[4];
            {
                uint32_t u0 = tf32r(ex2f(s[0])), u1 = tf32r(ex2f(s[1]));
                uint32_t u2 = tf32r(ex2f(s[2])), u3 = tf32r(ex2f(s[3]));
                rs[0] += __uint_as_float(u0) + __uint_as_float(u1);
                rs[1] += __uint_as_float(u2) + __uint_as_float(u3);
                a[0] = u0; a[1] = u2; a[2] = u1; a[3] = u3;
            }
            // O += P.V  (8 chan-tiles)
#pragma unroll
            for (int ct = 0; ct < 8; ++ct) {
                const uint32_t va = vbase + ct * 8 * VPITCHB + j * 32;
                const uint32_t vb0 = __float_as_uint(lds32(va));
                const uint32_t vb1 = __float_as_uint(lds32(va + 16));
                mma8(o[ct], a, vb0, vb1);
            }
        }
    }

    // row-sum reduce across tg lanes, then epilogue
#pragma unroll
    for (int i = 0; i < 2; ++i) {
        rs[i] += __shfl_xor_sync(0xffffffffu, rs[i], 1);
        rs[i] += __shfl_xor_sync(0xffffffffu, rs[i], 2);
    }
    const float inv0 = 1.0f / rs[0];
    const float inv1 = 1.0f / rs[1];

    const float* vres = value + (size_t)b * C_ * HW_;
    float* ob = out + (size_t)b * C_ * HW_;
#pragma unroll
    for (int ct = 0; ct < 8; ++ct) {
        const int ch = ct * 8 + 2 * tg;
        const size_t i00 = (size_t)ch * HW_ + rbase;   // (ch,   rbase)
        const size_t i01 = i00 + HW_;                  // (ch+1, rbase)
        const size_t i10 = i00 + 8;                    // (ch,   rbase+8)
        const size_t i11 = i01 + 8;                    // (ch+1, rbase+8)
        ob[i00] = o[ct][0] * inv0 + vres[i00];
        ob[i01] = o[ct][1] * inv0 + vres[i01];
        ob[i10] = o[ct][2] * inv1 + vres[i10];
        ob[i11] = o[ct][3] * inv1 + vres[i11];
    }
}

extern "C" void kernel_launch(void* const* d_in, const int* in_sizes, int n_in,
                              void* d_out, int out_size) {
    const float* query = (const float*)d_in[0];
    const float* value = (const float*)d_in[1];
    const float* Wq    = (const float*)d_in[2];
    const float* bq    = (const float*)d_in[3];
    const float* Wk    = (const float*)d_in[4];
    const float* bk    = (const float*)d_in[5];
    const float* Wv    = (const float*)d_in[6];
    const float* bv    = (const float*)d_in[7];
    float* out = (float*)d_out;

    cudaFuncSetAttribute(attn_kernel, cudaFuncAttributeMaxDynamicSharedMemorySize,
                         SMEM_TOTAL);

    dim3 pgrid(HW_ / 256, B_);
    proj_kernel<<<pgrid, 256>>>(query, value, Wq, bq, Wk, bk, Wv, bv);
    dim3 agrid(HW_ / 256, B_);
    attn_kernel<<<agrid, 512, SMEM_TOTAL>>>(value, out);
}

// round 6
// speedup vs baseline: 1.2893x; 1.2893x over previous
#include <cuda_runtime.h>
#include <cuda_fp16.h>
#include <cstdint>

#define B_   8
#define C_   64
#define HW_  4096
#define D_   8
#define TBN  128             // keys per tile
#define NT   (HW_ / TBN)     // 32
#define LOG2E 1.4426950408889634f

// ---------------- device scratch (allocation-free rule) ----------------
__device__ float  g_q[B_ * HW_ * D_];            // [b][n][8], pre-scaled by log2e
__device__ float  g_k[B_ * HW_ * D_];            // [b][m][8]
__device__ __align__(16) __half g_vh[B_ * C_ * HW_];  // [b][c][n]  channel-major fp16

// ---------------- smem geometry (attn) ----------------
#define KPITCH  48                    // bytes per key row (12 floats, conflict-free)
#define KBYTES  (TBN * KPITCH)        // 6144
#define VPITCH  272                   // bytes per chan row (256B data + pad, conflict-free)
#define VBYTES  (C_ * VPITCH)         // 17408
#define BUFSZ   (KBYTES + VBYTES)     // 23552
#define SMEM_TOTAL (3 * BUFSZ)        // 70656

// ---------------- helpers ----------------
__device__ __forceinline__ uint32_t smem_u32(const void* p) {
    uint32_t a;
    asm("{ .reg .u64 t; cvta.to.shared.u64 t, %1; cvt.u32.u64 %0, t; }" : "=r"(a) : "l"(p));
    return a;
}
__device__ __forceinline__ float ex2f(float x) {
    float r; asm("ex2.approx.f32 %0, %1;" : "=f"(r) : "f"(x)); return r;
}
__device__ __forceinline__ uint32_t tf32r(float f) {
    uint32_t u; asm("cvt.rna.tf32.f32 %0, %1;" : "=r"(u) : "f"(f)); return u;
}
__device__ __forceinline__ uint32_t f16x2(float hi, float lo) {  // packs {lo, hi}
    uint32_t r; asm("cvt.rn.f16x2.f32 %0, %1, %2;" : "=r"(r) : "f"(hi), "f"(lo));
    return r;
}
__device__ __forceinline__ float lds32(uint32_t a) {
    float v; asm volatile("ld.shared.f32 %0, [%1];" : "=f"(v) : "r"(a)); return v;
}
__device__ __forceinline__ uint32_t lds32u(uint32_t a) {
    uint32_t v; asm volatile("ld.shared.b32 %0, [%1];" : "=r"(v) : "r"(a)); return v;
}
__device__ __forceinline__ void cp16(uint32_t dst, const void* src) {
    asm volatile("cp.async.cg.shared.global [%0], [%1], 16;" :: "r"(dst), "l"(src) : "memory");
}
__device__ __forceinline__ void cp_commit() {
    asm volatile("cp.async.commit_group;" ::: "memory");
}
template <int N>
__device__ __forceinline__ void cp_wait() {
    asm volatile("cp.async.wait_group %0;" :: "n"(N) : "memory");
}
// S: m16n8k8 tf32
__device__ __forceinline__ void mma8(float* c, const uint32_t* a, uint32_t b0, uint32_t b1) {
    asm("mma.sync.aligned.m16n8k8.row.col.f32.tf32.tf32.f32 "
        "{%0,%1,%2,%3},{%4,%5,%6,%7},{%8,%9},{%0,%1,%2,%3};"
        : "+f"(c[0]), "+f"(c[1]), "+f"(c[2]), "+f"(c[3])
        : "r"(a[0]), "r"(a[1]), "r"(a[2]), "r"(a[3]), "r"(b0), "r"(b1));
}
// PV: m16n8k16 fp16 -> f32
__device__ __forceinline__ void mma16h(float* c, const uint32_t* a, uint32_t b0, uint32_t b1) {
    asm("mma.sync.aligned.m16n8k16.row.col.f32.f16.f16.f32 "
        "{%0,%1,%2,%3},{%4,%5,%6,%7},{%8,%9},{%0,%1,%2,%3};"
        : "+f"(c[0]), "+f"(c[1]), "+f"(c[2]), "+f"(c[3])
        : "r"(a[0]), "r"(a[1]), "r"(a[2]), "r"(a[3]), "r"(b0), "r"(b1));
}

// ---------------- packed f32x2 helpers (proj) ----------------
__device__ __forceinline__ unsigned long long fma2(unsigned long long a,
                                                   unsigned long long b,
                                                   unsigned long long c) {
    unsigned long long d;
    asm("fma.rn.f32x2 %0, %1, %2, %3;" : "=l"(d) : "l"(a), "l"(b), "l"(c));
    return d;
}
__device__ __forceinline__ unsigned long long pack2(float lo, float hi) {
    unsigned long long d;
    asm("mov.b64 %0, {%1, %2};" : "=l"(d) : "f"(lo), "f"(hi));
    return d;
}
__device__ __forceinline__ void unpack2(unsigned long long v, float& lo, float& hi) {
    asm("mov.b64 {%0, %1}, %2;" : "=f"(lo), "=f"(hi) : "l"(v));
}

// ---------------- Kernel 1: 1x1-conv projections ----------------
__global__ __launch_bounds__(256) void proj_kernel(
    const float* __restrict__ query, const float* __restrict__ value,
    const float* __restrict__ Wq, const float* __restrict__ bq,
    const float* __restrict__ Wk, const float* __restrict__ bk,
    const float* __restrict__ Wv, const float* __restrict__ bv) {
    __shared__ __align__(16) float sWqT[C_ * D_];
    __shared__ __align__(16) float sWkT[C_ * D_];
    __shared__ __align__(16) float sWvT[C_ * C_];
    __shared__ float sbq[D_], sbk[D_], sbv[C_];

    const int tid = threadIdx.x;
    for (int i = tid; i < D_ * C_; i += 256) {
        int o = i / C_, c = i % C_;
        sWqT[c * D_ + o] = Wq[i];
        sWkT[c * D_ + o] = Wk[i];
    }
    for (int i = tid; i < C_ * C_; i += 256) {
        int o = i / C_, c = i % C_;
        sWvT[c * C_ + o] = Wv[i];
    }
    if (tid < C_) sbv[tid] = bv[tid];
    if (tid < D_) { sbq[tid] = bq[tid]; sbk[tid] = bk[tid]; }
    __syncthreads();

    const int b = blockIdx.y;
    const int n = blockIdx.x * 256 + tid;
    const float* qbase = query + (size_t)b * C_ * HW_ + n;
    const float* vbase = value + (size_t)b * C_ * HW_ + n;

    float qa[D_], ka[D_];
    unsigned long long va2[C_ / 2];
#pragma unroll
    for (int d = 0; d < D_; ++d) { qa[d] = 0.f; ka[d] = 0.f; }
#pragma unroll
    for (int i = 0; i < C_ / 2; ++i) va2[i] = 0ULL;

#pragma unroll 2
    for (int c = 0; c < C_; ++c) {
        const float x = qbase[(size_t)c * HW_];
        const float y = vbase[(size_t)c * HW_];
        const float4 wq  = *(const float4*)&sWqT[c * D_];
        const float4 wq2 = *(const float4*)&sWqT[c * D_ + 4];
        const float4 wk  = *(const float4*)&sWkT[c * D_];
        const float4 wk2 = *(const float4*)&sWkT[c * D_ + 4];
        qa[0] += wq.x * x;  qa[1] += wq.y * x;  qa[2] += wq.z * x;  qa[3] += wq.w * x;
        qa[4] += wq2.x * x; qa[5] += wq2.y * x; qa[6] += wq2.z * x; qa[7] += wq2.w * x;
        ka[0] += wk.x * x;  ka[1] += wk.y * x;  ka[2] += wk.z * x;  ka[3] += wk.w * x;
        ka[4] += wk2.x * x; ka[5] += wk2.y * x; ka[6] += wk2.z * x; ka[7] += wk2.w * x;
        const unsigned long long y2 = pack2(y, y);
        const ulonglong2* wv = (const ulonglong2*)&sWvT[c * C_];
#pragma unroll
        for (int i = 0; i < C_ / 4; ++i) {
            ulonglong2 w = wv[i];
            va2[2 * i]     = fma2(w.x, y2, va2[2 * i]);
            va2[2 * i + 1] = fma2(w.y, y2, va2[2 * i + 1]);
        }
    }

    const size_t row = (size_t)b * HW_ + n;
    *(float4*)&g_q[row * D_] = make_float4(
        (qa[0] + sbq[0]) * LOG2E, (qa[1] + sbq[1]) * LOG2E,
        (qa[2] + sbq[2]) * LOG2E, (qa[3] + sbq[3]) * LOG2E);
    *(float4*)&g_q[row * D_ + 4] = make_float4(
        (qa[4] + sbq[4]) * LOG2E, (qa[5] + sbq[5]) * LOG2E,
        (qa[6] + sbq[6]) * LOG2E, (qa[7] + sbq[7]) * LOG2E);
    *(float4*)&g_k[row * D_] = make_float4(
        ka[0] + sbk[0], ka[1] + sbk[1], ka[2] + sbk[2], ka[3] + sbk[3]);
    *(float4*)&g_k[row * D_ + 4] = make_float4(
        ka[4] + sbk[4], ka[5] + sbk[5], ka[6] + sbk[6], ka[7] + sbk[7]);

    __half* vout = g_vh + (size_t)b * C_ * HW_ + n;
#pragma unroll
    for (int i = 0; i < C_ / 2; ++i) {
        float lo, hi;
        unpack2(va2[i], lo, hi);
        vout[(size_t)(2 * i) * HW_]     = __float2half_rn(lo + sbv[2 * i]);
        vout[(size_t)(2 * i + 1) * HW_] = __float2half_rn(hi + sbv[2 * i + 1]);
    }
}

// ---------------- tile loaders (512 threads) ----------------
__device__ __forceinline__ void load_k(uint32_t smb, int buf, int b, int m0, int tid) {
    if (tid < 256) {
        const float* ksrc = g_k + ((size_t)b * HW_ + m0) * D_ + tid * 4;
        uint32_t kdst = smb + buf * BUFSZ + (tid >> 1) * KPITCH + (tid & 1) * 16;
        cp16(kdst, ksrc);
    }
}
__device__ __forceinline__ void load_tile(uint32_t smb, int buf, int b, int m0, int tid) {
    load_k(smb, buf, b, m0, tid);
    const uint32_t vb = smb + buf * BUFSZ + KBYTES;
    const __half* vsrcb = g_vh + (size_t)b * C_ * HW_ + m0;
#pragma unroll
    for (int r = 0; r < 2; ++r) {
        int idx = tid + 512 * r;
        int ch = idx >> 4, sg = idx & 15;
        cp16(vb + ch * VPITCH + sg * 16, vsrcb + (size_t)ch * HW_ + sg * 8);
    }
}

// ---------------- Kernel 2: two-phase flash attention (tf32 S, fp16 PV) ----------------
// CTA: 512 threads, 16 warps x 16 query rows = 256 rows.  Grid: (16, 8).
__global__ __launch_bounds__(512, 1) void attn_kernel(
    const float* __restrict__ value, float* __restrict__ out) {
    extern __shared__ char sm[];
    const uint32_t smb = smem_u32(sm);
    const int tid = threadIdx.x;
    const int w = tid >> 5;
    const int lane = tid & 31;
    const int g = lane >> 2;           // group 0..7
    const int tg = lane & 3;           // thread-in-group 0..3
    const int b = blockIdx.y;
    const int n0 = blockIdx.x * 256;

    // Q fragment (A-frag, one m16 tile), tf32 — used in both phases
    const int rbase = n0 + w * 16 + g;   // rows rbase and rbase+8
    uint32_t qa[4];
    {
        const float* q0 = g_q + ((size_t)b * HW_ + rbase) * D_;
        const float* q1 = q0 + 8 * D_;
        qa[0] = tf32r(q0[tg]);
        qa[1] = tf32r(q1[tg]);
        qa[2] = tf32r(q0[tg + 4]);
        qa[3] = tf32r(q1[tg + 4]);
    }

    // ================= Phase 1: exact per-row max (K only) =================
    load_k(smb, 0, b, 0, tid);
    cp_commit();
    load_k(smb, 1, b, TBN, tid);
    cp_commit();

    float mx0 = -1e30f, mx1 = -1e30f;
    for (int t = 0; t < NT; ++t) {
        cp_wait<1>();
        __syncthreads();
        if (t + 2 < NT) load_k(smb, (t + 2) % 3, b, (t + 2) * TBN, tid);
        cp_commit();

        const uint32_t kbase = smb + (t % 3) * BUFSZ + g * KPITCH + tg * 4;
#pragma unroll
        for (int j = 0; j < 16; ++j) {
            const uint32_t kj = kbase + j * 8 * KPITCH;
            float s[4] = {0.f, 0.f, 0.f, 0.f};
            mma8(s, qa, __float_as_uint(lds32(kj)), __float_as_uint(lds32(kj + 16)));
            mx0 = fmaxf(mx0, fmaxf(s[0], s[1]));
            mx1 = fmaxf(mx1, fmaxf(s[2], s[3]));
        }
    }
    // reduce across the 4 tg lanes -> exact row max (log2 domain)
    mx0 = fmaxf(mx0, __shfl_xor_sync(0xffffffffu, mx0, 1));
    mx0 = fmaxf(mx0, __shfl_xor_sync(0xffffffffu, mx0, 2));
    mx1 = fmaxf(mx1, __shfl_xor_sync(0xffffffffu, mx1, 1));
    mx1 = fmaxf(mx1, __shfl_xor_sync(0xffffffffu, mx1, 2));

    // ================= Phase 2: softmax + PV =================
    load_tile(smb, 0, b, 0, tid);
    cp_commit();
    load_tile(smb, 1, b, TBN, tid);
    cp_commit();

    float o[8][4];
#pragma unroll
    for (int ct = 0; ct < 8; ++ct)
#pragma unroll
        for (int i = 0; i < 4; ++i) o[ct][i] = 0.f;
    float rs0 = 0.f, rs1 = 0.f;

    for (int t = 0; t < NT; ++t) {
        cp_wait<1>();
        __syncthreads();
        if (t + 2 < NT) load_tile(smb, (t + 2) % 3, b, (t + 2) * TBN, tid);
        cp_commit();

        const uint32_t base  = smb + (t % 3) * BUFSZ;
        const uint32_t kbase = base + g * KPITCH + tg * 4;
        const uint32_t vbase = base + KBYTES + g * VPITCH + tg * 4;

        // pipelined pair loop: 8 pairs of 16 keys; C init = -rowmax (free shift)
        float sA[4], sB[4];
        {
            const uint32_t kj = kbase;
            sA[0] = -mx0; sA[1] = -mx0; sA[2] = -mx1; sA[3] = -mx1;
            sB[0] = -mx0; sB[1] = -mx0; sB[2] = -mx1; sB[3] = -mx1;
            mma8(sA, qa, __float_as_uint(lds32(kj)), __float_as_uint(lds32(kj + 16)));
            mma8(sB, qa, __float_as_uint(lds32(kj + 8 * KPITCH)),
                 __float_as_uint(lds32(kj + 8 * KPITCH + 16)));
        }
#pragma unroll
        for (int jj = 0; jj < 8; ++jj) {
            float tA[4], tB[4];
            if (jj < 7) {   // issue S for next pair while converting current
                const uint32_t kj = kbase + (jj + 1) * 16 * KPITCH;
                tA[0] = -mx0; tA[1] = -mx0; tA[2] = -mx1; tA[3] = -mx1;
                tB[0] = -mx0; tB[1] = -mx0; tB[2] = -mx1; tB[3] = -mx1;
                mma8(tA, qa, __float_as_uint(lds32(kj)), __float_as_uint(lds32(kj + 16)));
                mma8(tB, qa, __float_as_uint(lds32(kj + 8 * KPITCH)),
                     __float_as_uint(lds32(kj + 8 * KPITCH + 16)));
            }
            // hoist V B-frags (independent of the exp chain)
            uint32_t vb0[8], vb1[8];
#pragma unroll
            for (int ct = 0; ct < 8; ++ct) {
                const uint32_t va = vbase + ct * 8 * VPITCH + jj * 32;
                vb0[ct] = lds32u(va);
                vb1[ct] = lds32u(va + 16);
            }
            // exp2 (all <= 1) -> fp16 pack; denom from pre-round floats
            const float pA0 = ex2f(sA[0]), pA1 = ex2f(sA[1]);
            const float pA2 = ex2f(sA[2]), pA3 = ex2f(sA[3]);
            const float pB0 = ex2f(sB[0]), pB1 = ex2f(sB[1]);
            const float pB2 = ex2f(sB[2]), pB3 = ex2f(sB[3]);
            rs0 += (pA0 + pA1) + (pB0 + pB1);
            rs1 += (pA2 + pA3) + (pB2 + pB3);
            uint32_t a[4];
            a[0] = f16x2(pA1, pA0);   // row g,   k = 2tg,2tg+1
            a[1] = f16x2(pA3, pA2);   // row g+8
            a[2] = f16x2(pB1, pB0);   // row g,   k = 2tg+8,2tg+9
            a[3] = f16x2(pB3, pB2);   // row g+8
#pragma unroll
            for (int ct = 0; ct < 8; ++ct) mma16h(o[ct], a, vb0[ct], vb1[ct]);
            if (jj < 7) {
#pragma unroll
                for (int i = 0; i < 4; ++i) { sA[i] = tA[i]; sB[i] = tB[i]; }
            }
        }
    }

    // row-sum reduce across tg lanes, then epilogue
    rs0 += __shfl_xor_sync(0xffffffffu, rs0, 1);
    rs0 += __shfl_xor_sync(0xffffffffu, rs0, 2);
    rs1 += __shfl_xor_sync(0xffffffffu, rs1, 1);
    rs1 += __shfl_xor_sync(0xffffffffu, rs1, 2);
    const float inv0 = 1.0f / rs0;
    const float inv1 = 1.0f / rs1;

    const float* vres = value + (size_t)b * C_ * HW_;
    float* ob = out + (size_t)b * C_ * HW_;
#pragma unroll
    for (int ct = 0; ct < 8; ++ct) {
        const int ch = ct * 8 + 2 * tg;
        const size_t i00 = (size_t)ch * HW_ + rbase;
        const size_t i01 = i00 + HW_;
        const size_t i10 = i00 + 8;
        const size_t i11 = i01 + 8;
        ob[i00] = o[ct][0] * inv0 + vres[i00];
        ob[i01] = o[ct][1] * inv0 + vres[i01];
        ob[i10] = o[ct][2] * inv1 + vres[i10];
        ob[i11] = o[ct][3] * inv1 + vres[i11];
    }
}

extern "C" void kernel_launch(void* const* d_in, const int* in_sizes, int n_in,
                              void* d_out, int out_size) {
    const float* query = (const float*)d_in[0];
    const float* value = (const float*)d_in[1];
    const float* Wq    = (const float*)d_in[2];
    const float* bq    = (const float*)d_in[3];
    const float* Wk    = (const float*)d_in[4];
    const float* bk    = (const float*)d_in[5];
    const float* Wv    = (const float*)d_in[6];
    const float* bv    = (const float*)d_in[7];
    float* out = (float*)d_out;

    cudaFuncSetAttribute(attn_kernel, cudaFuncAttributeMaxDynamicSharedMemorySize,
                         SMEM_TOTAL);

    dim3 pgrid(HW_ / 256, B_);
    proj_kernel<<<pgrid, 256>>>(query, value, Wq, bq, Wk, bk, Wv, bv);
    dim3 agrid(HW_ / 256, B_);
    attn_kernel<<<agrid, 512, SMEM_TOTAL>>>(value, out);
}

// round 7
// speedup vs baseline: 1.4599x; 1.1323x over previous
#include <cuda_runtime.h>
#include <cuda_fp16.h>
#include <cstdint>

#define B_   8
#define C_   64
#define HW_  4096
#define D_   8
#define TBN  128
#define NT   (HW_ / TBN)     // 32
#define LOG2E 1.4426950408889634f

// ---------------- device scratch (allocation-free rule) ----------------
__device__ __align__(16) __half g_qh[B_ * HW_ * D_];   // [b][n][8] fp16, pre-scaled log2e
__device__ __align__(16) __half g_kh[B_ * HW_ * D_];   // [b][m][8] fp16
__device__ __align__(16) __half g_vh[B_ * C_ * HW_];   // [b][c][n'] fp16, key-permuted

// ---------------- smem geometry (attn): V-only ring ----------------
#define VPITCH  288                   // bytes per chan row (256B data + 32 pad)
#define VBYTES  (C_ * VPITCH)         // 18432
#define SMEM_TOTAL (3 * VBYTES)       // 55296

// ---------------- helpers ----------------
__device__ __forceinline__ uint32_t smem_u32(const void* p) {
    uint32_t a;
    asm("{ .reg .u64 t; cvta.to.shared.u64 t, %1; cvt.u32.u64 %0, t; }" : "=r"(a) : "l"(p));
    return a;
}
__device__ __forceinline__ uint32_t f16x2(float hi, float lo) {  // d = {lo, hi}
    uint32_t r; asm("cvt.rn.f16x2.f32 %0, %1, %2;" : "=r"(r) : "f"(hi), "f"(lo));
    return r;
}
__device__ __forceinline__ uint32_t h2ex2(uint32_t x) {
    uint32_t r; asm("ex2.approx.f16x2 %0, %1;" : "=r"(r) : "r"(x)); return r;
}
__device__ __forceinline__ uint32_t hmax2(uint32_t a, uint32_t b) {
    uint32_t d; asm("max.f16x2 %0, %1, %2;" : "=r"(d) : "r"(a), "r"(b)); return d;
}
__device__ __forceinline__ void lds64(uint32_t& x, uint32_t& y, uint32_t a) {
    asm volatile("ld.shared.v2.b32 {%0, %1}, [%2];" : "=r"(x), "=r"(y) : "r"(a));
}
__device__ __forceinline__ void cp16(uint32_t dst, const void* src) {
    asm volatile("cp.async.cg.shared.global [%0], [%1], 16;" :: "r"(dst), "l"(src) : "memory");
}
__device__ __forceinline__ void cp_commit() {
    asm volatile("cp.async.commit_group;" ::: "memory");
}
template <int N>
__device__ __forceinline__ void cp_wait() {
    asm volatile("cp.async.wait_group %0;" :: "n"(N) : "memory");
}
// S (phase 1): m16n8k8 fp16 -> fp16 D (for max only)
__device__ __forceinline__ void mma8_h16d(uint32_t& d0, uint32_t& d1,
                                          uint32_t a0, uint32_t a1, uint32_t b0) {
    asm("mma.sync.aligned.m16n8k8.row.col.f16.f16.f16.f16 "
        "{%0,%1},{%2,%3},{%4},{%5,%6};"
        : "=r"(d0), "=r"(d1) : "r"(a0), "r"(a1), "r"(b0), "r"(0u), "r"(0u));
}
// S (phase 2): m16n8k8 fp16 -> fp32 accum
__device__ __forceinline__ void mma8_hf(float* c, uint32_t a0, uint32_t a1, uint32_t b0) {
    asm("mma.sync.aligned.m16n8k8.row.col.f32.f16.f16.f32 "
        "{%0,%1,%2,%3},{%4,%5},{%6},{%0,%1,%2,%3};"
        : "+f"(c[0]), "+f"(c[1]), "+f"(c[2]), "+f"(c[3])
        : "r"(a0), "r"(a1), "r"(b0));
}
// PV: m16n8k16 fp16 -> fp32
__device__ __forceinline__ void mma16h(float* c, const uint32_t* a, uint32_t b0, uint32_t b1) {
    asm("mma.sync.aligned.m16n8k16.row.col.f32.f16.f16.f32 "
        "{%0,%1,%2,%3},{%4,%5,%6,%7},{%8,%9},{%0,%1,%2,%3};"
        : "+f"(c[0]), "+f"(c[1]), "+f"(c[2]), "+f"(c[3])
        : "r"(a[0]), "r"(a[1]), "r"(a[2]), "r"(a[3]), "r"(b0), "r"(b1));
}

// ---------------- packed f32x2 helpers (proj) ----------------
__device__ __forceinline__ unsigned long long fma2(unsigned long long a,
                                                   unsigned long long b,
                                                   unsigned long long c) {
    unsigned long long d;
    asm("fma.rn.f32x2 %0, %1, %2, %3;" : "=l"(d) : "l"(a), "l"(b), "l"(c));
    return d;
}
__device__ __forceinline__ unsigned long long pack2(float lo, float hi) {
    unsigned long long d;
    asm("mov.b64 %0, {%1, %2};" : "=l"(d) : "f"(lo), "f"(hi));
    return d;
}
__device__ __forceinline__ void unpack2(unsigned long long v, float& lo, float& hi) {
    asm("mov.b64 {%0, %1}, %2;" : "=f"(lo), "=f"(hi) : "l"(v));
}

// key permutation within 16-groups so PV B-frags are contiguous 8B per thread
__device__ __forceinline__ int vperm(int k) {
    return (((k >> 1) & 3) << 2) | (((k >> 3) & 1) << 1) | (k & 1);
}

// ---------------- Kernel 1: 1x1-conv projections (fp16 outputs) ----------------
__global__ __launch_bounds__(256) void proj_kernel(
    const float* __restrict__ query, const float* __restrict__ value,
    const float* __restrict__ Wq, const float* __restrict__ bq,
    const float* __restrict__ Wk, const float* __restrict__ bk,
    const float* __restrict__ Wv, const float* __restrict__ bv) {
    __shared__ __align__(16) float sWqT[C_ * D_];
    __shared__ __align__(16) float sWkT[C_ * D_];
    __shared__ __align__(16) float sWvT[C_ * C_];
    __shared__ float sbq[D_], sbk[D_], sbv[C_];

    const int tid = threadIdx.x;
    for (int i = tid; i < D_ * C_; i += 256) {
        int o = i / C_, c = i % C_;
        sWqT[c * D_ + o] = Wq[i];
        sWkT[c * D_ + o] = Wk[i];
    }
    for (int i = tid; i < C_ * C_; i += 256) {
        int o = i / C_, c = i % C_;
        sWvT[c * C_ + o] = Wv[i];
    }
    if (tid < C_) sbv[tid] = bv[tid];
    if (tid < D_) { sbq[tid] = bq[tid]; sbk[tid] = bk[tid]; }
    __syncthreads();

    const int b = blockIdx.y;
    const int n = blockIdx.x * 256 + tid;
    const float* qbase = query + (size_t)b * C_ * HW_ + n;
    const float* vbase = value + (size_t)b * C_ * HW_ + n;

    float qa[D_], ka[D_];
    unsigned long long va2[C_ / 2];
#pragma unroll
    for (int d = 0; d < D_; ++d) { qa[d] = 0.f; ka[d] = 0.f; }
#pragma unroll
    for (int i = 0; i < C_ / 2; ++i) va2[i] = 0ULL;

#pragma unroll 2
    for (int c = 0; c < C_; ++c) {
        const float x = qbase[(size_t)c * HW_];
        const float y = vbase[(size_t)c * HW_];
        const float4 wq  = *(const float4*)&sWqT[c * D_];
        const float4 wq2 = *(const float4*)&sWqT[c * D_ + 4];
        const float4 wk  = *(const float4*)&sWkT[c * D_];
        const float4 wk2 = *(const float4*)&sWkT[c * D_ + 4];
        qa[0] += wq.x * x;  qa[1] += wq.y * x;  qa[2] += wq.z * x;  qa[3] += wq.w * x;
        qa[4] += wq2.x * x; qa[5] += wq2.y * x; qa[6] += wq2.z * x; qa[7] += wq2.w * x;
        ka[0] += wk.x * x;  ka[1] += wk.y * x;  ka[2] += wk.z * x;  ka[3] += wk.w * x;
        ka[4] += wk2.x * x; ka[5] += wk2.y * x; ka[6] += wk2.z * x; ka[7] += wk2.w * x;
        const unsigned long long y2 = pack2(y, y);
        const ulonglong2* wv = (const ulonglong2*)&sWvT[c * C_];
#pragma unroll
        for (int i = 0; i < C_ / 4; ++i) {
            ulonglong2 w = wv[i];
            va2[2 * i]     = fma2(w.x, y2, va2[2 * i]);
            va2[2 * i + 1] = fma2(w.y, y2, va2[2 * i + 1]);
        }
    }

    const size_t row = (size_t)b * HW_ + n;
    __half qh[8], kh[8];
#pragma unroll
    for (int d = 0; d < D_; ++d) {
        qh[d] = __float2half_rn((qa[d] + sbq[d]) * LOG2E);
        kh[d] = __float2half_rn(ka[d] + sbk[d]);
    }
    *(uint4*)&g_qh[row * D_] = *(uint4*)qh;
    *(uint4*)&g_kh[row * D_] = *(uint4*)kh;

    // V: fp16, key-permuted position within 16-groups
    const int npr = (n & ~15) | vperm(n & 15);
    __half* vout = g_vh + (size_t)b * C_ * HW_ + npr;
#pragma unroll
    for (int i = 0; i < C_ / 2; ++i) {
        float lo, hi;
        unpack2(va2[i], lo, hi);
        vout[(size_t)(2 * i) * HW_]     = __float2half_rn(lo + sbv[2 * i]);
        vout[(size_t)(2 * i + 1) * HW_] = __float2half_rn(hi + sbv[2 * i + 1]);
    }
}

// ---------------- V tile loader (512 threads) ----------------
__device__ __forceinline__ void load_v(uint32_t smb, int buf, int b, int m0, int tid) {
    const uint32_t vb = smb + buf * VBYTES;
    const __half* src = g_vh + (size_t)b * C_ * HW_ + m0;
#pragma unroll
    for (int r = 0; r < 2; ++r) {
        int idx = tid + 512 * r;
        int ch = idx >> 4, sg = idx & 15;
        cp16(vb + ch * VPITCH + sg * 16, src + (size_t)ch * HW_ + sg * 8);
    }
}

// ---------------- Kernel 2: flash attention (fp16 mma everywhere) ----------------
// CTA: 512 threads, 16 warps x 16 query rows = 256 rows.  Grid: (16, 8).
__global__ __launch_bounds__(512, 1) void attn_kernel(
    const float* __restrict__ value, float* __restrict__ out) {
    extern __shared__ char sm[];
    const uint32_t smb = smem_u32(sm);
    const int tid = threadIdx.x;
    const int w = tid >> 5;
    const int lane = tid & 31;
    const int g = lane >> 2;
    const int tg = lane & 3;
    const int b = blockIdx.y;
    const int n0 = blockIdx.x * 256;
    const int rbase = n0 + w * 16 + g;

    // Q A-frag (fp16 k8): 2 regs
    const uint32_t* qptr = (const uint32_t*)g_qh;
    const uint32_t qa0 = __ldg(qptr + (size_t)(b * HW_ + rbase) * 4 + tg);
    const uint32_t qa1 = __ldg(qptr + (size_t)(b * HW_ + rbase + 8) * 4 + tg);

    // start V prologue loads (overlap with phase 1)
    load_v(smb, 0, b, 0, tid);
    cp_commit();
    load_v(smb, 1, b, TBN, tid);
    cp_commit();

    // ================= Phase 1: per-row max, registers only =================
    // K B-frag for j-th 8-key group: uint at [b*HW*4 + j*32 + g*4 + tg]
    const uint32_t* kgp = (const uint32_t*)g_kh + (size_t)b * HW_ * 4 + g * 4 + tg;
    uint32_t mh0 = 0xFC00FC00u, mh1 = 0xFC00FC00u;   // (-inf, -inf)
#pragma unroll 8
    for (int j = 0; j < HW_ / 8; ++j) {
        const uint32_t kb = __ldg(kgp + j * 32);
        uint32_t d0, d1;
        mma8_h16d(d0, d1, qa0, qa1, kb);
        mh0 = hmax2(mh0, d0);
        mh1 = hmax2(mh1, d1);
    }
    float mx0, mx1;
    {
        __half2 h0 = *reinterpret_cast<__half2*>(&mh0);
        __half2 h1 = *reinterpret_cast<__half2*>(&mh1);
        mx0 = fmaxf(__low2float(h0), __high2float(h0));
        mx1 = fmaxf(__low2float(h1), __high2float(h1));
    }
    mx0 = fmaxf(mx0, __shfl_xor_sync(0xffffffffu, mx0, 1));
    mx0 = fmaxf(mx0, __shfl_xor_sync(0xffffffffu, mx0, 2));
    mx1 = fmaxf(mx1, __shfl_xor_sync(0xffffffffu, mx1, 1));
    mx1 = fmaxf(mx1, __shfl_xor_sync(0xffffffffu, mx1, 2));

    // ================= Phase 2: softmax + PV =================
    float o[8][4];
#pragma unroll
    for (int ct = 0; ct < 8; ++ct)
#pragma unroll
        for (int i = 0; i < 4; ++i) o[ct][i] = 0.f;
    float rs0 = 0.f, rs1 = 0.f;

    for (int t = 0; t < NT; ++t) {
        cp_wait<1>();
        __syncthreads();
        if (t + 2 < NT) load_v(smb, (t + 2) % 3, b, (t + 2) * TBN, tid);
        cp_commit();

        const uint32_t base = smb + (t % 3) * VBYTES;
        const uint32_t vwb  = base + g * VPITCH + tg * 8;
        const uint32_t* kt  = kgp + t * 512;   // 16 j-groups per tile

        // preload K frags for pairs 0,1; rotate 2-deep
        uint32_t kc[2][2];
        kc[0][0] = __ldg(kt);       kc[0][1] = __ldg(kt + 32);
        kc[1][0] = __ldg(kt + 64);  kc[1][1] = __ldg(kt + 96);

        float sA[4], sB[4];
        sA[0] = -mx0; sA[1] = -mx0; sA[2] = -mx1; sA[3] = -mx1;
        sB[0] = -mx0; sB[1] = -mx0; sB[2] = -mx1; sB[3] = -mx1;
        mma8_hf(sA, qa0, qa1, kc[0][0]);
        mma8_hf(sB, qa0, qa1, kc[0][1]);

#pragma unroll
        for (int jj = 0; jj < 8; ++jj) {
            const int sl = jj & 1, sl1 = (jj + 1) & 1;
            if (jj < 6) {   // prefetch K frags for pair jj+2 into freed slot
                kc[sl][0] = __ldg(kt + (2 * jj + 4) * 32);
                kc[sl][1] = __ldg(kt + (2 * jj + 5) * 32);
            }
            float tA[4], tB[4];
            if (jj < 7) {   // S for next pair while converting current
                tA[0] = -mx0; tA[1] = -mx0; tA[2] = -mx1; tA[3] = -mx1;
                tB[0] = -mx0; tB[1] = -mx0; tB[2] = -mx1; tB[3] = -mx1;
                mma8_hf(tA, qa0, qa1, kc[sl1][0]);
                mma8_hf(tB, qa0, qa1, kc[sl1][1]);
            }
            // V B-frags: contiguous 8B per thread (global key-perm) -> LDS.64
            uint32_t vb0[8], vb1[8];
#pragma unroll
            for (int ct = 0; ct < 8; ++ct)
                lds64(vb0[ct], vb1[ct], vwb + ct * (8 * VPITCH) + jj * 32);
            // s -> fp16 pack -> packed exp2: output IS the PV A-frag
            uint32_t a[4];
            a[0] = h2ex2(f16x2(sA[1], sA[0]));
            a[1] = h2ex2(f16x2(sA[3], sA[2]));
            a[2] = h2ex2(f16x2(sB[1], sB[0]));
            a[3] = h2ex2(f16x2(sB[3], sB[2]));
            // denom from the SAME fp16 p values (bias cancels with numerator)
            {
                __half2 p0 = *reinterpret_cast<__half2*>(&a[0]);
                __half2 p1 = *reinterpret_cast<__half2*>(&a[1]);
                __half2 p2 = *reinterpret_cast<__half2*>(&a[2]);
                __half2 p3 = *reinterpret_cast<__half2*>(&a[3]);
                float2 f0 = __half22float2(p0), f1 = __half22float2(p1);
                float2 f2 = __half22float2(p2), f3 = __half22float2(p3);
                rs0 += (f0.x + f0.y) + (f2.x + f2.y);
                rs1 += (f1.x + f1.y) + (f3.x + f3.y);
            }
#pragma unroll
            for (int ct = 0; ct < 8; ++ct) mma16h(o[ct], a, vb0[ct], vb1[ct]);
            if (jj < 7) {
#pragma unroll
                for (int i = 0; i < 4; ++i) { sA[i] = tA[i]; sB[i] = tB[i]; }
            }
        }
    }

    // reduce row sums across tg lanes, epilogue
    rs0 += __shfl_xor_sync(0xffffffffu, rs0, 1);
    rs0 += __shfl_xor_sync(0xffffffffu, rs0, 2);
    rs1 += __shfl_xor_sync(0xffffffffu, rs1, 1);
    rs1 += __shfl_xor_sync(0xffffffffu, rs1, 2);
    const float inv0 = 1.0f / rs0;
    const float inv1 = 1.0f / rs1;

    const float* vres = value + (size_t)b * C_ * HW_;
    float* ob = out + (size_t)b * C_ * HW_;
#pragma unroll
    for (int ct = 0; ct < 8; ++ct) {
        const int ch = ct * 8 + 2 * tg;
        const size_t i00 = (size_t)ch * HW_ + rbase;
        const size_t i01 = i00 + HW_;
        const size_t i10 = i00 + 8;
        const size_t i11 = i01 + 8;
        ob[i00] = o[ct][0] * inv0 + vres[i00];
        ob[i01] = o[ct][1] * inv0 + vres[i01];
        ob[i10] = o[ct][2] * inv1 + vres[i10];
        ob[i11] = o[ct][3] * inv1 + vres[i11];
    }
}

extern "C" void kernel_launch(void* const* d_in, const int* in_sizes, int n_in,
                              void* d_out, int out_size) {
    const float* query = (const float*)d_in[0];
    const float* value = (const float*)d_in[1];
    const float* Wq    = (const float*)d_in[2];
    const float* bq    = (const float*)d_in[3];
    const float* Wk    = (const float*)d_in[4];
    const float* bk    = (const float*)d_in[5];
    const float* Wv    = (const float*)d_in[6];
    const float* bv    = (const float*)d_in[7];
    float* out = (float*)d_out;

    cudaFuncSetAttribute(attn_kernel, cudaFuncAttributeMaxDynamicSharedMemorySize,
                         SMEM_TOTAL);

    dim3 pgrid(HW_ / 256, B_);
    proj_kernel<<<pgrid, 256>>>(query, value, Wq, bq, Wk, bk, Wv, bv);
    dim3 agrid(HW_ / 256, B_);
    attn_kernel<<<agrid, 512, SMEM_TOTAL>>>(value, out);
}